// round 3
// baseline (speedup 1.0000x reference)
#include <cuda_runtime.h>
#include <cstdint>
#include <math.h>

#define TOKENS 8192
#define DMODEL 1024
#define DFF    4096
#define RANK   128
#define MT     64
#define SV     132   // smem stride for 128-wide-K tiles (132%8==4 -> conflict-free frags)
#define SU     68    // smem stride for 64-wide-K tiles

// ---- tf32 scratch (prep-kernel outputs) ----
__device__ uint32_t g_xt[TOKENS * DMODEL];   // x as tf32
__device__ uint32_t g_v1[DFF * RANK];        // cfc_V as tf32          [f][r]
__device__ uint32_t g_v2[DMODEL * RANK];     // cp_V as tf32           [d][r]
__device__ uint32_t g_u1t[RANK * DMODEL];    // (cfc_U * S)^T as tf32  [r][d]
__device__ uint32_t g_u2t[RANK * DFF];       // (cp_U * S2)^T as tf32  [r][f]

__device__ __forceinline__ uint32_t f2tf(float f) {
    uint32_t u;
    asm("cvt.rna.tf32.f32 %0, %1;" : "=r"(u) : "f"(f));
    return u;
}

__device__ __forceinline__ void mma8(float* c,
                                     uint32_t a0, uint32_t a1, uint32_t a2, uint32_t a3,
                                     uint32_t b0, uint32_t b1) {
    asm volatile(
        "mma.sync.aligned.m16n8k8.row.col.f32.tf32.tf32.f32 "
        "{%0,%1,%2,%3}, {%4,%5,%6,%7}, {%8,%9}, {%0,%1,%2,%3};\n"
        : "+f"(c[0]), "+f"(c[1]), "+f"(c[2]), "+f"(c[3])
        : "r"(a0), "r"(a1), "r"(a2), "r"(a3), "r"(b0), "r"(b1));
}

__device__ __forceinline__ void cpa16(uint32_t dst, const void* src) {
    asm volatile("cp.async.cg.shared.global [%0], [%1], 16;\n"
                 :: "r"(dst), "l"(src) : "memory");
}
#define CPA_COMMIT() asm volatile("cp.async.commit_group;\n" ::: "memory")
#define CPA_WAIT1()  asm volatile("cp.async.wait_group 1;\n" ::: "memory")

__device__ __forceinline__ float gelu_exact(float v) {
    return 0.5f * v * (1.f + erff(v * 0.7071067811865476f));
}

// ---------------- prep kernels ----------------
__global__ void prep_x_kernel(const float* __restrict__ x) {
    int i = blockIdx.x * 256 + threadIdx.x;         // 2M float4s
    float4 v = ((const float4*)x)[i];
    ((uint4*)g_xt)[i] = make_uint4(f2tf(v.x), f2tf(v.y), f2tf(v.z), f2tf(v.w));
}

__global__ void prep_w_kernel(const float* __restrict__ cfc_U, const float* __restrict__ cfc_S,
                              const float* __restrict__ cfc_V,
                              const float* __restrict__ cp_U,  const float* __restrict__ cp_S,
                              const float* __restrict__ cp_V) {
    int b = blockIdx.x, t = threadIdx.x;
    if (b < 512) {                                   // v1: 4096x128, float4 cvt
        int i = b * 256 + t;
        float4 v = ((const float4*)cfc_V)[i];
        ((uint4*)g_v1)[i] = make_uint4(f2tf(v.x), f2tf(v.y), f2tf(v.z), f2tf(v.w));
    } else if (b < 640) {                            // v2: 1024x128, float4 cvt
        int i = (b - 512) * 256 + t;
        float4 v = ((const float4*)cp_V)[i];
        ((uint4*)g_v2)[i] = make_uint4(f2tf(v.x), f2tf(v.y), f2tf(v.z), f2tf(v.w));
    } else if (b < 1152) {                           // u1t: transpose + fold S
        int o = (b - 640) * 256 + t;                 // o = r*1024 + d
        int r = o >> 10, d = o & 1023;
        g_u1t[o] = f2tf(cfc_U[d * RANK + r] * cfc_S[r]);
    } else {                                         // u2t: transpose + fold S2
        int o = (b - 1152) * 256 + t;                // o = r*4096 + f
        int r = o >> 12, f = o & 4095;
        g_u2t[o] = f2tf(cp_U[f * RANK + r] * cp_S[r]);
    }
}

// ---------------- main fused kernel ----------------
// smem map (uint32 units):
//  t1s:0 (64x132)  hs:8448 (64x68)  vbuf:12800/21248 (64x132 x2)
//  ubuf:29696/38400 (128x68 x2)     bias:47104/47168 (64 x2)   total 47232
__global__ void __launch_bounds__(512, 1)
fused_lowrank_mlp_kernel(const float* __restrict__ cfc_b,
                         const float* __restrict__ cp_b,
                         float* __restrict__ out)
{
    extern __shared__ uint32_t sm[];
    const uint32_t smb = (uint32_t)__cvta_generic_to_shared(sm);
    uint32_t* t1s   = sm;
    uint32_t* hs    = sm + 8448;
    uint32_t* vb_[2] = { sm + 12800, sm + 21248 };
    uint32_t* ub_[2] = { sm + 29696, sm + 38400 };
    float*    bb_[2] = { (float*)(sm + 47104), (float*)(sm + 47168) };
    const uint32_t VBA[2] = { smb + 12800u * 4, smb + 21248u * 4 };
    const uint32_t UBA[2] = { smb + 29696u * 4, smb + 38400u * 4 };
    const uint32_t BBA[2] = { smb + 47104u * 4, smb + 47168u * 4 };

    const int tid  = threadIdx.x;
    const int lane = tid & 31;
    const int warp = tid >> 5;
    const int wr   = warp & 3;        // 4 row groups
    const int wc   = warp >> 2;       // 4 col groups
    const int wm   = wr * 16;
    const int qr   = lane >> 2;
    const int qc   = lane & 3;
    const int m0   = blockIdx.x * MT;

    // ---- staging helpers (each thread: <=9 cp.asyncs per stage) ----
    auto stage1 = [&](int ci, int b) {   // x chunk [64x64] + u1t chunk [128x64]
        int kc = ci * 64;
        #pragma unroll
        for (int i = 0; i < 2; i++) {
            int idx = tid + i * 512; int r = idx >> 4, s = idx & 15;
            cpa16(VBA[b] + (uint32_t)(r * SV + s * 4) * 4,
                  g_xt + (size_t)(m0 + r) * DMODEL + kc + s * 4);
        }
        #pragma unroll
        for (int i = 0; i < 4; i++) {
            int idx = tid + i * 512; int r = idx >> 4, s = idx & 15;
            cpa16(UBA[b] + (uint32_t)(r * SU + s * 4) * 4,
                  g_u1t + (size_t)r * DMODEL + kc + s * 4);
        }
    };
    auto stage2 = [&](int it, int b) {   // v1 chunk [64x128] + u2t chunk [128x64] + bias
        int f0 = it * 64;
        #pragma unroll
        for (int i = 0; i < 4; i++) {
            int idx = tid + i * 512; int r = idx >> 5, s = idx & 31;
            cpa16(VBA[b] + (uint32_t)(r * SV + s * 4) * 4,
                  g_v1 + (size_t)(f0 + r) * RANK + s * 4);
        }
        #pragma unroll
        for (int i = 0; i < 4; i++) {
            int idx = tid + i * 512; int r = idx >> 4, s = idx & 15;
            cpa16(UBA[b] + (uint32_t)(r * SU + s * 4) * 4,
                  g_u2t + (size_t)r * DFF + f0 + s * 4);
        }
        if (tid < 16) cpa16(BBA[b] + tid * 16, cfc_b + f0 + tid * 4);
    };
    auto stage3 = [&](int dc, int b) {   // v2 chunk [64x128] + bias
        int d0 = dc * 64;
        #pragma unroll
        for (int i = 0; i < 4; i++) {
            int idx = tid + i * 512; int r = idx >> 5, s = idx & 31;
            cpa16(VBA[b] + (uint32_t)(r * SV + s * 4) * 4,
                  g_v2 + (size_t)(d0 + r) * RANK + s * 4);
        }
        if (tid < 16) cpa16(BBA[b] + tid * 16, cp_b + d0 + tid * 4);
    };

    // ================= Phase 1: t1 = x @ (U1*S)  [64 x 128] =================
    float acc1[4][4];
    #pragma unroll
    for (int i = 0; i < 4; i++)
        #pragma unroll
        for (int j = 0; j < 4; j++) acc1[i][j] = 0.f;

    stage1(0, 0); CPA_COMMIT();
    stage1(1, 1); CPA_COMMIT();

    for (int ci = 0; ci < 16; ci++) {
        int b = ci & 1;
        CPA_WAIT1(); __syncthreads();
        const uint32_t* xb = vb_[b];
        const uint32_t* ub = ub_[b];
        #pragma unroll
        for (int ks = 0; ks < 8; ks++) {
            int k0 = ks * 8;
            uint32_t a0 = xb[(wm + qr) * SV + k0 + qc];
            uint32_t a1 = xb[(wm + qr + 8) * SV + k0 + qc];
            uint32_t a2 = xb[(wm + qr) * SV + k0 + qc + 4];
            uint32_t a3 = xb[(wm + qr + 8) * SV + k0 + qc + 4];
            #pragma unroll
            for (int nt = 0; nt < 4; nt++) {
                int n0 = wc * 32 + nt * 8;
                uint32_t b0 = ub[(n0 + qr) * SU + k0 + qc];
                uint32_t b1 = ub[(n0 + qr) * SU + k0 + qc + 4];
                mma8(acc1[nt], a0, a1, a2, a3, b0, b1);
            }
        }
        __syncthreads();
        if (ci + 2 < 16) stage1(ci + 2, b);
        CPA_COMMIT();
    }

    // prologue for phase 2 overlaps the t1 epilogue
    stage2(0, 0); CPA_COMMIT();
    stage2(1, 1); CPA_COMMIT();

    #pragma unroll
    for (int nt = 0; nt < 4; nt++) {
        int c0 = wc * 32 + nt * 8 + 2 * qc;
        t1s[(wm + qr) * SV + c0]         = f2tf(acc1[nt][0]);
        t1s[(wm + qr) * SV + c0 + 1]     = f2tf(acc1[nt][1]);
        t1s[(wm + qr + 8) * SV + c0]     = f2tf(acc1[nt][2]);
        t1s[(wm + qr + 8) * SV + c0 + 1] = f2tf(acc1[nt][3]);
    }

    // ========== Phase 2: t2 = sum_f gelu(t1@V1^T + b) @ (U2*S2) ==========
    float t2a[4][4];
    #pragma unroll
    for (int i = 0; i < 4; i++)
        #pragma unroll
        for (int j = 0; j < 4; j++) t2a[i][j] = 0.f;

    for (int it = 0; it < 64; it++) {
        int b = it & 1;
        CPA_WAIT1(); __syncthreads();
        const uint32_t* vp = vb_[b];
        const uint32_t* up = ub_[b];
        const float*    bp = bb_[b];

        // GEMM2: h[64x64] = t1 @ Vchunk^T  (K=128)
        float ha[2][4];
        #pragma unroll
        for (int i = 0; i < 2; i++)
            #pragma unroll
            for (int j = 0; j < 4; j++) ha[i][j] = 0.f;
        #pragma unroll 4
        for (int ks = 0; ks < 16; ks++) {
            int k0 = ks * 8;
            uint32_t a0 = t1s[(wm + qr) * SV + k0 + qc];
            uint32_t a1 = t1s[(wm + qr + 8) * SV + k0 + qc];
            uint32_t a2 = t1s[(wm + qr) * SV + k0 + qc + 4];
            uint32_t a3 = t1s[(wm + qr + 8) * SV + k0 + qc + 4];
            #pragma unroll
            for (int nt = 0; nt < 2; nt++) {
                int n0 = wc * 16 + nt * 8;
                uint32_t b0 = vp[(n0 + qr) * SV + k0 + qc];
                uint32_t b1 = vp[(n0 + qr) * SV + k0 + qc + 4];
                mma8(ha[nt], a0, a1, a2, a3, b0, b1);
            }
        }

        // bias + exact GELU -> hs (tf32)
        #pragma unroll
        for (int nt = 0; nt < 2; nt++) {
            int c0 = wc * 16 + nt * 8 + 2 * qc;
            float bf0 = bp[c0], bf1 = bp[c0 + 1];
            float v00 = gelu_exact(ha[nt][0] + bf0);
            float v01 = gelu_exact(ha[nt][1] + bf1);
            float v10 = gelu_exact(ha[nt][2] + bf0);
            float v11 = gelu_exact(ha[nt][3] + bf1);
            hs[(wm + qr) * SU + c0]         = f2tf(v00);
            hs[(wm + qr) * SU + c0 + 1]     = f2tf(v01);
            hs[(wm + qr + 8) * SU + c0]     = f2tf(v10);
            hs[(wm + qr + 8) * SU + c0 + 1] = f2tf(v11);
        }
        __syncthreads();

        // GEMM3: t2 += h @ (U2*S2)chunk  (K=64)
        #pragma unroll
        for (int ks = 0; ks < 8; ks++) {
            int k0 = ks * 8;
            uint32_t a0 = hs[(wm + qr) * SU + k0 + qc];
            uint32_t a1 = hs[(wm + qr + 8) * SU + k0 + qc];
            uint32_t a2 = hs[(wm + qr) * SU + k0 + qc + 4];
            uint32_t a3 = hs[(wm + qr + 8) * SU + k0 + qc + 4];
            #pragma unroll
            for (int nt = 0; nt < 4; nt++) {
                int n0 = wc * 32 + nt * 8;
                uint32_t b0 = up[(n0 + qr) * SU + k0 + qc];
                uint32_t b1 = up[(n0 + qr) * SU + k0 + qc + 4];
                mma8(t2a[nt], a0, a1, a2, a3, b0, b1);
            }
        }
        __syncthreads();
        if (it + 2 < 64) stage2(it + 2, b);
        CPA_COMMIT();
    }

    // prologue for phase 3 overlaps the t2 epilogue
    stage3(0, 0); CPA_COMMIT();
    stage3(1, 1); CPA_COMMIT();

    #pragma unroll
    for (int nt = 0; nt < 4; nt++) {
        int c0 = wc * 32 + nt * 8 + 2 * qc;
        t1s[(wm + qr) * SV + c0]         = f2tf(t2a[nt][0]);
        t1s[(wm + qr) * SV + c0 + 1]     = f2tf(t2a[nt][1]);
        t1s[(wm + qr + 8) * SV + c0]     = f2tf(t2a[nt][2]);
        t1s[(wm + qr + 8) * SV + c0 + 1] = f2tf(t2a[nt][3]);
    }

    // ================= Phase 3: out = t2 @ V2^T + b2 =================
    for (int dc = 0; dc < 16; dc++) {
        int b = dc & 1, d0 = dc * 64;
        CPA_WAIT1(); __syncthreads();
        const uint32_t* vp = vb_[b];
        const float*    bp = bb_[b];

        float oa[2][4];
        #pragma unroll
        for (int i = 0; i < 2; i++)
            #pragma unroll
            for (int j = 0; j < 4; j++) oa[i][j] = 0.f;
        #pragma unroll 4
        for (int ks = 0; ks < 16; ks++) {
            int k0 = ks * 8;
            uint32_t a0 = t1s[(wm + qr) * SV + k0 + qc];
            uint32_t a1 = t1s[(wm + qr + 8) * SV + k0 + qc];
            uint32_t a2 = t1s[(wm + qr) * SV + k0 + qc + 4];
            uint32_t a3 = t1s[(wm + qr + 8) * SV + k0 + qc + 4];
            #pragma unroll
            for (int nt = 0; nt < 2; nt++) {
                int n0 = wc * 16 + nt * 8;
                uint32_t b0 = vp[(n0 + qr) * SV + k0 + qc];
                uint32_t b1 = vp[(n0 + qr) * SV + k0 + qc + 4];
                mma8(oa[nt], a0, a1, a2, a3, b0, b1);
            }
        }

        #pragma unroll
        for (int nt = 0; nt < 2; nt++) {
            int cc = wc * 16 + nt * 8 + 2 * qc;
            float bf0 = bp[cc], bf1 = bp[cc + 1];
            size_t ro = (size_t)(m0 + wm + qr) * DMODEL + d0 + cc;
            *(float2*)(out + ro) = make_float2(oa[nt][0] + bf0, oa[nt][1] + bf1);
            *(float2*)(out + ro + (size_t)8 * DMODEL) =
                make_float2(oa[nt][2] + bf0, oa[nt][3] + bf1);
        }
        __syncthreads();
        if (dc + 2 < 16) stage3(dc + 2, b);
        CPA_COMMIT();
    }
}

extern "C" void kernel_launch(void* const* d_in, const int* in_sizes, int n_in,
                              void* d_out, int out_size)
{
    const float* x     = (const float*)d_in[0];
    const float* cfc_U = (const float*)d_in[1];
    const float* cfc_S = (const float*)d_in[2];
    const float* cfc_V = (const float*)d_in[3];
    const float* cfc_b = (const float*)d_in[4];
    const float* cp_U  = (const float*)d_in[5];
    const float* cp_S  = (const float*)d_in[6];
    const float* cp_V  = (const float*)d_in[7];
    const float* cp_b  = (const float*)d_in[8];
    float* out = (float*)d_out;

    prep_x_kernel<<<TOKENS * DMODEL / 1024, 256>>>(x);
    prep_w_kernel<<<3200, 256>>>(cfc_U, cfc_S, cfc_V, cp_U, cp_S, cp_V);

    const int smem_bytes = 47232 * 4;   // 188928 B
    cudaFuncSetAttribute(fused_lowrank_mlp_kernel,
                         cudaFuncAttributeMaxDynamicSharedMemorySize, smem_bytes);
    fused_lowrank_mlp_kernel<<<TOKENS / MT, 512, smem_bytes>>>(cfc_b, cp_b, out);
}

// round 4
// speedup vs baseline: 1.0004x; 1.0004x over previous
#include <cuda_runtime.h>
#include <cstdint>
#include <math.h>

#define TOKENS 8192
#define DMODEL 1024
#define DFF    4096
#define RANK   128
#define MT     64
#define SV     132   // smem stride for 128-wide-K tiles (132%8==4 -> conflict-free frags)
#define SU     68    // smem stride for 64-wide-K tiles

// ---- tf32 scratch (prep-kernel outputs) ----
__device__ uint32_t g_xt[TOKENS * DMODEL];   // x as tf32
__device__ uint32_t g_v1[DFF * RANK];        // cfc_V as tf32          [f][r]
__device__ uint32_t g_v2[DMODEL * RANK];     // cp_V as tf32           [d][r]
__device__ uint32_t g_u1t[RANK * DMODEL];    // (cfc_U * S)^T as tf32  [r][d]
__device__ uint32_t g_u2t[RANK * DFF];       // (cp_U * S2)^T as tf32  [r][f]

__device__ __forceinline__ uint32_t f2tf(float f) {
    uint32_t u;
    asm("cvt.rna.tf32.f32 %0, %1;" : "=r"(u) : "f"(f));
    return u;
}

__device__ __forceinline__ void mma8(float* c,
                                     uint32_t a0, uint32_t a1, uint32_t a2, uint32_t a3,
                                     uint32_t b0, uint32_t b1) {
    asm volatile(
        "mma.sync.aligned.m16n8k8.row.col.f32.tf32.tf32.f32 "
        "{%0,%1,%2,%3}, {%4,%5,%6,%7}, {%8,%9}, {%0,%1,%2,%3};\n"
        : "+f"(c[0]), "+f"(c[1]), "+f"(c[2]), "+f"(c[3])
        : "r"(a0), "r"(a1), "r"(a2), "r"(a3), "r"(b0), "r"(b1));
}

__device__ __forceinline__ void cpa16(uint32_t dst, const void* src) {
    asm volatile("cp.async.cg.shared.global [%0], [%1], 16;\n"
                 :: "r"(dst), "l"(src) : "memory");
}
#define CPA_COMMIT() asm volatile("cp.async.commit_group;\n" ::: "memory")
#define CPA_WAIT1()  asm volatile("cp.async.wait_group 1;\n" ::: "memory")

__device__ __forceinline__ float gelu_exact(float v) {
    return 0.5f * v * (1.f + erff(v * 0.7071067811865476f));
}

// ---------------- prep kernels ----------------
__global__ void prep_x_kernel(const float* __restrict__ x) {
    int i = blockIdx.x * 256 + threadIdx.x;         // 2M float4s
    float4 v = ((const float4*)x)[i];
    ((uint4*)g_xt)[i] = make_uint4(f2tf(v.x), f2tf(v.y), f2tf(v.z), f2tf(v.w));
}

__global__ void prep_w_kernel(const float* __restrict__ cfc_U, const float* __restrict__ cfc_S,
                              const float* __restrict__ cfc_V,
                              const float* __restrict__ cp_U,  const float* __restrict__ cp_S,
                              const float* __restrict__ cp_V) {
    int b = blockIdx.x, t = threadIdx.x;
    if (b < 512) {                                   // v1: 4096x128, float4 cvt
        int i = b * 256 + t;
        float4 v = ((const float4*)cfc_V)[i];
        ((uint4*)g_v1)[i] = make_uint4(f2tf(v.x), f2tf(v.y), f2tf(v.z), f2tf(v.w));
    } else if (b < 640) {                            // v2: 1024x128, float4 cvt
        int i = (b - 512) * 256 + t;
        float4 v = ((const float4*)cp_V)[i];
        ((uint4*)g_v2)[i] = make_uint4(f2tf(v.x), f2tf(v.y), f2tf(v.z), f2tf(v.w));
    } else if (b < 1152) {                           // u1t: transpose + fold S
        int o = (b - 640) * 256 + t;                 // o = r*1024 + d
        int r = o >> 10, d = o & 1023;
        g_u1t[o] = f2tf(cfc_U[d * RANK + r] * cfc_S[r]);
    } else {                                         // u2t: transpose + fold S2
        int o = (b - 1152) * 256 + t;                // o = r*4096 + f
        int r = o >> 12, f = o & 4095;
        g_u2t[o] = f2tf(cp_U[f * RANK + r] * cp_S[r]);
    }
}

// ---------------- main fused kernel ----------------
// smem map (uint32 units):
//  t1s:0 (64x132)  hs:8448 (64x68)  vbuf:12800/21248 (64x132 x2)
//  ubuf:29696/38400 (128x68 x2)     bias:47104/47168 (64 x2)   total 47232
__global__ void __launch_bounds__(512, 1)
fused_lowrank_mlp_kernel(const float* __restrict__ cfc_b,
                         const float* __restrict__ cp_b,
                         float* __restrict__ out)
{
    extern __shared__ uint32_t sm[];
    const uint32_t smb = (uint32_t)__cvta_generic_to_shared(sm);
    uint32_t* t1s   = sm;
    uint32_t* hs    = sm + 8448;
    uint32_t* vb_[2] = { sm + 12800, sm + 21248 };
    uint32_t* ub_[2] = { sm + 29696, sm + 38400 };
    float*    bb_[2] = { (float*)(sm + 47104), (float*)(sm + 47168) };
    const uint32_t VBA[2] = { smb + 12800u * 4, smb + 21248u * 4 };
    const uint32_t UBA[2] = { smb + 29696u * 4, smb + 38400u * 4 };
    const uint32_t BBA[2] = { smb + 47104u * 4, smb + 47168u * 4 };

    const int tid  = threadIdx.x;
    const int lane = tid & 31;
    const int warp = tid >> 5;
    const int wr   = warp & 3;        // 4 row groups
    const int wc   = warp >> 2;       // 4 col groups
    const int wm   = wr * 16;
    const int qr   = lane >> 2;
    const int qc   = lane & 3;
    const int m0   = blockIdx.x * MT;

    // ---- staging helpers (each thread: <=9 cp.asyncs per stage) ----
    auto stage1 = [&](int ci, int b) {   // x chunk [64x64] + u1t chunk [128x64]
        int kc = ci * 64;
        #pragma unroll
        for (int i = 0; i < 2; i++) {
            int idx = tid + i * 512; int r = idx >> 4, s = idx & 15;
            cpa16(VBA[b] + (uint32_t)(r * SV + s * 4) * 4,
                  g_xt + (size_t)(m0 + r) * DMODEL + kc + s * 4);
        }
        #pragma unroll
        for (int i = 0; i < 4; i++) {
            int idx = tid + i * 512; int r = idx >> 4, s = idx & 15;
            cpa16(UBA[b] + (uint32_t)(r * SU + s * 4) * 4,
                  g_u1t + (size_t)r * DMODEL + kc + s * 4);
        }
    };
    auto stage2 = [&](int it, int b) {   // v1 chunk [64x128] + u2t chunk [128x64] + bias
        int f0 = it * 64;
        #pragma unroll
        for (int i = 0; i < 4; i++) {
            int idx = tid + i * 512; int r = idx >> 5, s = idx & 31;
            cpa16(VBA[b] + (uint32_t)(r * SV + s * 4) * 4,
                  g_v1 + (size_t)(f0 + r) * RANK + s * 4);
        }
        #pragma unroll
        for (int i = 0; i < 4; i++) {
            int idx = tid + i * 512; int r = idx >> 4, s = idx & 15;
            cpa16(UBA[b] + (uint32_t)(r * SU + s * 4) * 4,
                  g_u2t + (size_t)r * DFF + f0 + s * 4);
        }
        if (tid < 16) cpa16(BBA[b] + tid * 16, cfc_b + f0 + tid * 4);
    };
    auto stage3 = [&](int dc, int b) {   // v2 chunk [64x128] + bias
        int d0 = dc * 64;
        #pragma unroll
        for (int i = 0; i < 4; i++) {
            int idx = tid + i * 512; int r = idx >> 5, s = idx & 31;
            cpa16(VBA[b] + (uint32_t)(r * SV + s * 4) * 4,
                  g_v2 + (size_t)(d0 + r) * RANK + s * 4);
        }
        if (tid < 16) cpa16(BBA[b] + tid * 16, cp_b + d0 + tid * 4);
    };

    // ================= Phase 1: t1 = x @ (U1*S)  [64 x 128] =================
    float acc1[4][4];
    #pragma unroll
    for (int i = 0; i < 4; i++)
        #pragma unroll
        for (int j = 0; j < 4; j++) acc1[i][j] = 0.f;

    stage1(0, 0); CPA_COMMIT();
    stage1(1, 1); CPA_COMMIT();

    for (int ci = 0; ci < 16; ci++) {
        int b = ci & 1;
        CPA_WAIT1(); __syncthreads();
        const uint32_t* xb = vb_[b];
        const uint32_t* ub = ub_[b];
        #pragma unroll
        for (int ks = 0; ks < 8; ks++) {
            int k0 = ks * 8;
            uint32_t a0 = xb[(wm + qr) * SV + k0 + qc];
            uint32_t a1 = xb[(wm + qr + 8) * SV + k0 + qc];
            uint32_t a2 = xb[(wm + qr) * SV + k0 + qc + 4];
            uint32_t a3 = xb[(wm + qr + 8) * SV + k0 + qc + 4];
            #pragma unroll
            for (int nt = 0; nt < 4; nt++) {
                int n0 = wc * 32 + nt * 8;
                uint32_t b0 = ub[(n0 + qr) * SU + k0 + qc];
                uint32_t b1 = ub[(n0 + qr) * SU + k0 + qc + 4];
                mma8(acc1[nt], a0, a1, a2, a3, b0, b1);
            }
        }
        __syncthreads();
        if (ci + 2 < 16) stage1(ci + 2, b);
        CPA_COMMIT();
    }

    // prologue for phase 2 overlaps the t1 epilogue
    stage2(0, 0); CPA_COMMIT();
    stage2(1, 1); CPA_COMMIT();

    #pragma unroll
    for (int nt = 0; nt < 4; nt++) {
        int c0 = wc * 32 + nt * 8 + 2 * qc;
        t1s[(wm + qr) * SV + c0]         = f2tf(acc1[nt][0]);
        t1s[(wm + qr) * SV + c0 + 1]     = f2tf(acc1[nt][1]);
        t1s[(wm + qr + 8) * SV + c0]     = f2tf(acc1[nt][2]);
        t1s[(wm + qr + 8) * SV + c0 + 1] = f2tf(acc1[nt][3]);
    }

    // ========== Phase 2: t2 = sum_f gelu(t1@V1^T + b) @ (U2*S2) ==========
    float t2a[4][4];
    #pragma unroll
    for (int i = 0; i < 4; i++)
        #pragma unroll
        for (int j = 0; j < 4; j++) t2a[i][j] = 0.f;

    for (int it = 0; it < 64; it++) {
        int b = it & 1;
        CPA_WAIT1(); __syncthreads();
        const uint32_t* vp = vb_[b];
        const uint32_t* up = ub_[b];
        const float*    bp = bb_[b];

        // GEMM2: h[64x64] = t1 @ Vchunk^T  (K=128)
        float ha[2][4];
        #pragma unroll
        for (int i = 0; i < 2; i++)
            #pragma unroll
            for (int j = 0; j < 4; j++) ha[i][j] = 0.f;
        #pragma unroll 4
        for (int ks = 0; ks < 16; ks++) {
            int k0 = ks * 8;
            uint32_t a0 = t1s[(wm + qr) * SV + k0 + qc];
            uint32_t a1 = t1s[(wm + qr + 8) * SV + k0 + qc];
            uint32_t a2 = t1s[(wm + qr) * SV + k0 + qc + 4];
            uint32_t a3 = t1s[(wm + qr + 8) * SV + k0 + qc + 4];
            #pragma unroll
            for (int nt = 0; nt < 2; nt++) {
                int n0 = wc * 16 + nt * 8;
                uint32_t b0 = vp[(n0 + qr) * SV + k0 + qc];
                uint32_t b1 = vp[(n0 + qr) * SV + k0 + qc + 4];
                mma8(ha[nt], a0, a1, a2, a3, b0, b1);
            }
        }

        // bias + exact GELU -> hs (tf32)
        #pragma unroll
        for (int nt = 0; nt < 2; nt++) {
            int c0 = wc * 16 + nt * 8 + 2 * qc;
            float bf0 = bp[c0], bf1 = bp[c0 + 1];
            float v00 = gelu_exact(ha[nt][0] + bf0);
            float v01 = gelu_exact(ha[nt][1] + bf1);
            float v10 = gelu_exact(ha[nt][2] + bf0);
            float v11 = gelu_exact(ha[nt][3] + bf1);
            hs[(wm + qr) * SU + c0]         = f2tf(v00);
            hs[(wm + qr) * SU + c0 + 1]     = f2tf(v01);
            hs[(wm + qr + 8) * SU + c0]     = f2tf(v10);
            hs[(wm + qr + 8) * SU + c0 + 1] = f2tf(v11);
        }
        __syncthreads();

        // GEMM3: t2 += h @ (U2*S2)chunk  (K=64)
        #pragma unroll
        for (int ks = 0; ks < 8; ks++) {
            int k0 = ks * 8;
            uint32_t a0 = hs[(wm + qr) * SU + k0 + qc];
            uint32_t a1 = hs[(wm + qr + 8) * SU + k0 + qc];
            uint32_t a2 = hs[(wm + qr) * SU + k0 + qc + 4];
            uint32_t a3 = hs[(wm + qr + 8) * SU + k0 + qc + 4];
            #pragma unroll
            for (int nt = 0; nt < 4; nt++) {
                int n0 = wc * 32 + nt * 8;
                uint32_t b0 = up[(n0 + qr) * SU + k0 + qc];
                uint32_t b1 = up[(n0 + qr) * SU + k0 + qc + 4];
                mma8(t2a[nt], a0, a1, a2, a3, b0, b1);
            }
        }
        __syncthreads();
        if (it + 2 < 64) stage2(it + 2, b);
        CPA_COMMIT();
    }

    // prologue for phase 3 overlaps the t2 epilogue
    stage3(0, 0); CPA_COMMIT();
    stage3(1, 1); CPA_COMMIT();

    #pragma unroll
    for (int nt = 0; nt < 4; nt++) {
        int c0 = wc * 32 + nt * 8 + 2 * qc;
        t1s[(wm + qr) * SV + c0]         = f2tf(t2a[nt][0]);
        t1s[(wm + qr) * SV + c0 + 1]     = f2tf(t2a[nt][1]);
        t1s[(wm + qr + 8) * SV + c0]     = f2tf(t2a[nt][2]);
        t1s[(wm + qr + 8) * SV + c0 + 1] = f2tf(t2a[nt][3]);
    }

    // ================= Phase 3: out = t2 @ V2^T + b2 =================
    for (int dc = 0; dc < 16; dc++) {
        int b = dc & 1, d0 = dc * 64;
        CPA_WAIT1(); __syncthreads();
        const uint32_t* vp = vb_[b];
        const float*    bp = bb_[b];

        float oa[2][4];
        #pragma unroll
        for (int i = 0; i < 2; i++)
            #pragma unroll
            for (int j = 0; j < 4; j++) oa[i][j] = 0.f;
        #pragma unroll 4
        for (int ks = 0; ks < 16; ks++) {
            int k0 = ks * 8;
            uint32_t a0 = t1s[(wm + qr) * SV + k0 + qc];
            uint32_t a1 = t1s[(wm + qr + 8) * SV + k0 + qc];
            uint32_t a2 = t1s[(wm + qr) * SV + k0 + qc + 4];
            uint32_t a3 = t1s[(wm + qr + 8) * SV + k0 + qc + 4];
            #pragma unroll
            for (int nt = 0; nt < 2; nt++) {
                int n0 = wc * 16 + nt * 8;
                uint32_t b0 = vp[(n0 + qr) * SV + k0 + qc];
                uint32_t b1 = vp[(n0 + qr) * SV + k0 + qc + 4];
                mma8(oa[nt], a0, a1, a2, a3, b0, b1);
            }
        }

        #pragma unroll
        for (int nt = 0; nt < 2; nt++) {
            int cc = wc * 16 + nt * 8 + 2 * qc;
            float bf0 = bp[cc], bf1 = bp[cc + 1];
            size_t ro = (size_t)(m0 + wm + qr) * DMODEL + d0 + cc;
            *(float2*)(out + ro) = make_float2(oa[nt][0] + bf0, oa[nt][1] + bf1);
            *(float2*)(out + ro + (size_t)8 * DMODEL) =
                make_float2(oa[nt][2] + bf0, oa[nt][3] + bf1);
        }
        __syncthreads();
        if (dc + 2 < 16) stage3(dc + 2, b);
        CPA_COMMIT();
    }
}

extern "C" void kernel_launch(void* const* d_in, const int* in_sizes, int n_in,
                              void* d_out, int out_size)
{
    const float* x     = (const float*)d_in[0];
    const float* cfc_U = (const float*)d_in[1];
    const float* cfc_S = (const float*)d_in[2];
    const float* cfc_V = (const float*)d_in[3];
    const float* cfc_b = (const float*)d_in[4];
    const float* cp_U  = (const float*)d_in[5];
    const float* cp_S  = (const float*)d_in[6];
    const float* cp_V  = (const float*)d_in[7];
    const float* cp_b  = (const float*)d_in[8];
    float* out = (float*)d_out;

    prep_x_kernel<<<TOKENS * DMODEL / 1024, 256>>>(x);
    prep_w_kernel<<<3200, 256>>>(cfc_U, cfc_S, cfc_V, cp_U, cp_S, cp_V);

    const int smem_bytes = 47232 * 4;   // 188928 B
    cudaFuncSetAttribute(fused_lowrank_mlp_kernel,
                         cudaFuncAttributeMaxDynamicSharedMemorySize, smem_bytes);
    fused_lowrank_mlp_kernel<<<TOKENS / MT, 512, smem_bytes>>>(cfc_b, cp_b, out);
}

// round 8
// speedup vs baseline: 1.2671x; 1.2666x over previous
#include <cuda_runtime.h>
#include <cstdint>
#include <math.h>

#define TOKENS 8192
#define DMODEL 1024
#define DFF    4096
#define RANK   128
#define MT     64

// smem strides in words; both == 16 (mod 32) -> conflict-free LDS.128 fragments
#define SK128 144
#define SK64  80
// smem word offsets
#define W_SA  0                    // t1 / t2 tile: 64 x 144
#define W_SH  9216                 // h tile: 64 x 80
#define W_WB0 14336                // staging buffer 0 (19456 words)
#define W_WB1 33792                // staging buffer 1
#define WB_U  9216                 // U-part offset inside a staging buffer
#define SMEM_WORDS 53248           // 212992 bytes

// ---- k-permuted tf32 weight scratch (prep outputs) ----
__device__ uint32_t g_v1[DFF * RANK];      // cfc_V          [f][perm(r)]
__device__ uint32_t g_v2[DMODEL * RANK];   // cp_V           [d][perm(r)]
__device__ uint32_t g_u1t[RANK * DMODEL];  // (cfc_U*S)^T    [r][perm(d)]
__device__ uint32_t g_u2t[RANK * DFF];     // (cp_U*S2)^T    [r][perm(f)]

__device__ __forceinline__ int pcid(int c) {           // permute low 4 bits
    return (c & ~15) | ((c & 3) << 2) | ((c >> 2) & 3);
}
__device__ __forceinline__ uint32_t f2tf(float f) {
    uint32_t u; asm("cvt.rna.tf32.f32 %0, %1;" : "=r"(u) : "f"(f)); return u;
}
__device__ __forceinline__ float gelu_exact(float v) {
    return 0.5f * v * (1.f + erff(v * 0.7071067811865476f));
}
__device__ __forceinline__ void mma8(float* c,
                                     uint32_t a0, uint32_t a1, uint32_t a2, uint32_t a3,
                                     uint32_t b0, uint32_t b1) {
    asm volatile(
        "mma.sync.aligned.m16n8k8.row.col.f32.tf32.tf32.f32 "
        "{%0,%1,%2,%3}, {%4,%5,%6,%7}, {%8,%9}, {%0,%1,%2,%3};\n"
        : "+f"(c[0]), "+f"(c[1]), "+f"(c[2]), "+f"(c[3])
        : "r"(a0), "r"(a1), "r"(a2), "r"(a3), "r"(b0), "r"(b1));
}
__device__ __forceinline__ void cpa16(uint32_t dst, const void* src) {
    asm volatile("cp.async.cg.shared.global [%0], [%1], 16;\n" :: "r"(dst), "l"(src) : "memory");
}
#define CPA_COMMIT() asm volatile("cp.async.commit_group;\n" ::: "memory")
#define CPA_WAIT1()  asm volatile("cp.async.wait_group 1;\n" ::: "memory")

// Generic warp GEMM piece: mt=2 fixed (rows mrow..mrow+31), NT n-tiles of 8,
// KP k-pairs (K = KP*16). A,B in k-permuted layout; one LDS.128 feeds 2 k-steps.
template<int NT, int KP, int SA_, int SB_>
__device__ __forceinline__ void gemm_tile(const uint32_t* __restrict__ A,
                                          const uint32_t* __restrict__ B,
                                          int mrow, int ncol, int qr, int qc,
                                          float (*acc)[4])
{
    #pragma unroll
    for (int kp = 0; kp < KP; kp++) {
        const int kb = kp * 16 + qc * 4;
        uint4 a[4];
        #pragma unroll
        for (int mi = 0; mi < 2; mi++) {
            a[mi * 2 + 0] = *(const uint4*)(A + (mrow + mi * 16 + qr)     * SA_ + kb);
            a[mi * 2 + 1] = *(const uint4*)(A + (mrow + mi * 16 + qr + 8) * SA_ + kb);
        }
        uint4 b[NT];
        #pragma unroll
        for (int nt = 0; nt < NT; nt++)
            b[nt] = *(const uint4*)(B + (ncol + nt * 8 + qr) * SB_ + kb);
        #pragma unroll
        for (int mi = 0; mi < 2; mi++)
            #pragma unroll
            for (int nt = 0; nt < NT; nt++) {
                float* c = acc[mi * NT + nt];
                mma8(c, a[mi*2].x, a[mi*2+1].x, a[mi*2].y, a[mi*2+1].y, b[nt].x, b[nt].y);
                mma8(c, a[mi*2].z, a[mi*2+1].z, a[mi*2].w, a[mi*2+1].w, b[nt].z, b[nt].w);
            }
    }
}

// ---------------- prep: convert weights to tf32, fold S, transpose, k-permute ----------------
__global__ void prep_w_kernel(const float* __restrict__ cfc_U, const float* __restrict__ cfc_S,
                              const float* __restrict__ cfc_V,
                              const float* __restrict__ cp_U,  const float* __restrict__ cp_S,
                              const float* __restrict__ cp_V) {
    int b = blockIdx.x, t = threadIdx.x;
    if (b < 512) {                       // g_v1: [f][perm(r)]
        int i = b * 256 + t;             // float4 over DFF*RANK
        int row = i >> 5, j = i & 31;
        float4 v = ((const float4*)cfc_V)[i];
        uint32_t* d = g_v1 + (size_t)row * RANK;
        int c = j * 4;
        d[pcid(c + 0)] = f2tf(v.x); d[pcid(c + 1)] = f2tf(v.y);
        d[pcid(c + 2)] = f2tf(v.z); d[pcid(c + 3)] = f2tf(v.w);
    } else if (b < 640) {                // g_v2: [d][perm(r)]
        int i = (b - 512) * 256 + t;
        int row = i >> 5, j = i & 31;
        float4 v = ((const float4*)cp_V)[i];
        uint32_t* d = g_v2 + (size_t)row * RANK;
        int c = j * 4;
        d[pcid(c + 0)] = f2tf(v.x); d[pcid(c + 1)] = f2tf(v.y);
        d[pcid(c + 2)] = f2tf(v.z); d[pcid(c + 3)] = f2tf(v.w);
    } else if (b < 1152) {               // g_u1t: [r][perm(d)] = U1[d][r]*S[r]
        int o = (b - 640) * 256 + t;     // o = r*1024 + d
        int r = o >> 10, d = o & 1023;
        g_u1t[(size_t)r * DMODEL + pcid(d)] = f2tf(cfc_U[(size_t)d * RANK + r] * cfc_S[r]);
    } else {                             // g_u2t: [r][perm(f)] = U2[f][r]*S2[r]
        int o = (b - 1152) * 256 + t;    // o = r*4096 + f
        int r = o >> 12, f = o & 4095;
        g_u2t[(size_t)r * DFF + pcid(f)] = f2tf(cp_U[(size_t)f * RANK + r] * cp_S[r]);
    }
}

// ---------------- main fused kernel ----------------
__global__ void __launch_bounds__(256, 1)
fused_lowrank_mlp_kernel(const float* __restrict__ x,
                         const float* __restrict__ cfc_b,
                         const float* __restrict__ cp_b,
                         float* __restrict__ out)
{
    extern __shared__ uint32_t sm[];
    uint32_t* SA = sm + W_SA;
    uint32_t* SH = sm + W_SH;
    uint32_t* WB[2] = { sm + W_WB0, sm + W_WB1 };
    const uint32_t smb = (uint32_t)__cvta_generic_to_shared(sm);
    const uint32_t WBA[2] = { smb + W_WB0 * 4u, smb + W_WB1 * 4u };

    const int tid  = threadIdx.x;
    const int lane = tid & 31;
    const int warp = tid >> 5;
    const int qr   = lane >> 2;
    const int qc   = lane & 3;
    const int mg   = warp & 1;          // 2 row groups of 32
    const int ng   = warp >> 1;         // 4 col groups
    const int mrow = mg * 32;
    const int m0   = blockIdx.x * MT;

    // ---- staging helpers ----
    // U1 chunk [128 r x 64 d] -> WB[b]+WB_U, stride 80
    auto stage_u1 = [&](int ci, int b) {
        const uint32_t* src = g_u1t + ci * 64;
        #pragma unroll
        for (int i = 0; i < 8; i++) {
            int u = tid + i * 256; int row = u >> 4, p = u & 15;
            cpa16(WBA[b] + (WB_U + row * SK64 + p * 4) * 4u,
                  src + (size_t)row * DMODEL + p * 4);
        }
    };
    // V1 chunk [64 f x 128 r] -> WB[b], stride 144 ; U2 chunk [128 r x 64 f] -> +WB_U
    auto stage_2 = [&](int it, int b) {
        const uint32_t* sv = g_v1 + (size_t)it * 64 * RANK;
        #pragma unroll
        for (int i = 0; i < 8; i++) {
            int u = tid + i * 256; int row = u >> 5, p = u & 31;
            cpa16(WBA[b] + (row * SK128 + p * 4) * 4u, sv + (size_t)row * RANK + p * 4);
        }
        const uint32_t* su = g_u2t + it * 64;
        #pragma unroll
        for (int i = 0; i < 8; i++) {
            int u = tid + i * 256; int row = u >> 4, p = u & 15;
            cpa16(WBA[b] + (WB_U + row * SK64 + p * 4) * 4u,
                  su + (size_t)row * DFF + p * 4);
        }
    };
    // V2 chunk [64 d x 128 r] -> WB[b]
    auto stage_3 = [&](int dc, int b) {
        const uint32_t* sv = g_v2 + (size_t)dc * 64 * RANK;
        #pragma unroll
        for (int i = 0; i < 8; i++) {
            int u = tid + i * 256; int row = u >> 5, p = u & 31;
            cpa16(WBA[b] + (row * SK128 + p * 4) * 4u, sv + (size_t)row * RANK + p * 4);
        }
    };

    // x chunk [64 tok x 64 d]: LDG float4 -> regs; STS permuted tf32 (stride 80)
    float4 xr[4];
    auto ldx = [&](int ci) {
        if (ci < 16) {
            #pragma unroll
            for (int i = 0; i < 4; i++) {
                int idx = tid + i * 256; int row = idx >> 4, j = idx & 15;
                xr[i] = *(const float4*)(x + (size_t)(m0 + row) * DMODEL + ci * 64 + j * 4);
            }
        }
    };
    auto stx = [&](int b) {
        #pragma unroll
        for (int i = 0; i < 4; i++) {
            int idx = tid + i * 256; int row = idx >> 4, j = idx & 15;
            uint32_t* d = WB[b] + row * SK64 + (j >> 2) * 16 + (j & 3);
            d[0]  = f2tf(xr[i].x);
            d[4]  = f2tf(xr[i].y);
            d[8]  = f2tf(xr[i].z);
            d[12] = f2tf(xr[i].w);
        }
    };

    // ================= Phase 1: t1[64x128] = x @ (U1*S) =================
    float acc1[8][4];
    #pragma unroll
    for (int i = 0; i < 8; i++)
        #pragma unroll
        for (int j = 0; j < 4; j++) acc1[i][j] = 0.f;

    ldx(0); stx(0); stage_u1(0, 0); CPA_COMMIT();
    ldx(1); stx(1); stage_u1(1, 1); CPA_COMMIT();
    ldx(2);

    for (int ci = 0; ci < 16; ci++) {
        int b = ci & 1;
        CPA_WAIT1();
        __syncthreads();
        gemm_tile<4, 4, SK64, SK64>(WB[b], WB[b] + WB_U, mrow, ng * 32, qr, qc, acc1);
        __syncthreads();
        if (ci + 2 < 16) { stx(b); stage_u1(ci + 2, b); }
        CPA_COMMIT();
        ldx(ci + 3);
    }

    // t1 epilogue -> SA (k-permuted, stride 144)
    #pragma unroll
    for (int mi = 0; mi < 2; mi++)
        #pragma unroll
        for (int nt = 0; nt < 4; nt++) {
            int c0 = ng * 32 + nt * 8 + 2 * qc;
            int r0 = mrow + mi * 16 + qr;
            float* a = acc1[mi * 4 + nt];
            SA[r0 * SK128 + pcid(c0)]           = f2tf(a[0]);
            SA[r0 * SK128 + pcid(c0 + 1)]       = f2tf(a[1]);
            SA[(r0 + 8) * SK128 + pcid(c0)]     = f2tf(a[2]);
            SA[(r0 + 8) * SK128 + pcid(c0 + 1)] = f2tf(a[3]);
        }

    stage_2(0, 0); CPA_COMMIT();
    stage_2(1, 1); CPA_COMMIT();

    // ===== Phase 2: 64 f-chunks of 64; t2 accumulates in registers =====
    float t2a[8][4];
    #pragma unroll
    for (int i = 0; i < 8; i++)
        #pragma unroll
        for (int j = 0; j < 4; j++) t2a[i][j] = 0.f;

    for (int it = 0; it < 64; it++) {
        int b = it & 1;
        CPA_WAIT1();
        __syncthreads();

        // GEMM2: h[64x64] = t1 @ V1c^T   (K=128)
        float ha[4][4];
        #pragma unroll
        for (int i = 0; i < 4; i++)
            #pragma unroll
            for (int j = 0; j < 4; j++) ha[i][j] = 0.f;
        gemm_tile<2, 8, SK128, SK128>(SA, WB[b], mrow, ng * 16, qr, qc, ha);

        // bias + exact GELU -> SH (k-permuted, stride 80)
        #pragma unroll
        for (int mi = 0; mi < 2; mi++)
            #pragma unroll
            for (int nt = 0; nt < 2; nt++) {
                int c0 = ng * 16 + nt * 8 + 2 * qc;
                int fb = it * 64 + c0;
                float b0 = __ldg(cfc_b + fb), b1 = __ldg(cfc_b + fb + 1);
                int r0 = mrow + mi * 16 + qr;
                float* a = ha[mi * 2 + nt];
                SH[r0 * SK64 + pcid(c0)]           = f2tf(gelu_exact(a[0] + b0));
                SH[r0 * SK64 + pcid(c0 + 1)]       = f2tf(gelu_exact(a[1] + b1));
                SH[(r0 + 8) * SK64 + pcid(c0)]     = f2tf(gelu_exact(a[2] + b0));
                SH[(r0 + 8) * SK64 + pcid(c0 + 1)] = f2tf(gelu_exact(a[3] + b1));
            }
        __syncthreads();

        // GEMM3: t2[64x128] += h @ (U2*S2)c   (K=64)
        gemm_tile<4, 4, SK64, SK64>(SH, WB[b] + WB_U, mrow, ng * 32, qr, qc, t2a);
        __syncthreads();

        if (it + 2 < 64) stage_2(it + 2, b);
        CPA_COMMIT();
    }

    // t2 epilogue -> SA (reuse)
    #pragma unroll
    for (int mi = 0; mi < 2; mi++)
        #pragma unroll
        for (int nt = 0; nt < 4; nt++) {
            int c0 = ng * 32 + nt * 8 + 2 * qc;
            int r0 = mrow + mi * 16 + qr;
            float* a = t2a[mi * 4 + nt];
            SA[r0 * SK128 + pcid(c0)]           = f2tf(a[0]);
            SA[r0 * SK128 + pcid(c0 + 1)]       = f2tf(a[1]);
            SA[(r0 + 8) * SK128 + pcid(c0)]     = f2tf(a[2]);
            SA[(r0 + 8) * SK128 + pcid(c0 + 1)] = f2tf(a[3]);
        }

    stage_3(0, 0); CPA_COMMIT();
    stage_3(1, 1); CPA_COMMIT();

    // ================= Phase 3: out = t2 @ V2^T + b2 =================
    for (int dc = 0; dc < 16; dc++) {
        int b = dc & 1;
        CPA_WAIT1();
        __syncthreads();

        float oa[4][4];
        #pragma unroll
        for (int i = 0; i < 4; i++)
            #pragma unroll
            for (int j = 0; j < 4; j++) oa[i][j] = 0.f;
        gemm_tile<2, 8, SK128, SK128>(SA, WB[b], mrow, ng * 16, qr, qc, oa);

        #pragma unroll
        for (int mi = 0; mi < 2; mi++)
            #pragma unroll
            for (int nt = 0; nt < 2; nt++) {
                int c0 = ng * 16 + nt * 8 + 2 * qc;
                int db = dc * 64 + c0;
                float b0 = __ldg(cp_b + db), b1 = __ldg(cp_b + db + 1);
                int r0 = m0 + mrow + mi * 16 + qr;
                float* a = oa[mi * 2 + nt];
                *(float2*)(out + (size_t)r0 * DMODEL + db) =
                    make_float2(a[0] + b0, a[1] + b1);
                *(float2*)(out + (size_t)(r0 + 8) * DMODEL + db) =
                    make_float2(a[2] + b0, a[3] + b1);
            }
        __syncthreads();
        if (dc + 2 < 16) stage_3(dc + 2, b);
        CPA_COMMIT();
    }
}

extern "C" void kernel_launch(void* const* d_in, const int* in_sizes, int n_in,
                              void* d_out, int out_size)
{
    const float* x     = (const float*)d_in[0];
    const float* cfc_U = (const float*)d_in[1];
    const float* cfc_S = (const float*)d_in[2];
    const float* cfc_V = (const float*)d_in[3];
    const float* cfc_b = (const float*)d_in[4];
    const float* cp_U  = (const float*)d_in[5];
    const float* cp_S  = (const float*)d_in[6];
    const float* cp_V  = (const float*)d_in[7];
    const float* cp_b  = (const float*)d_in[8];
    float* out = (float*)d_out;

    prep_w_kernel<<<3200, 256>>>(cfc_U, cfc_S, cfc_V, cp_U, cp_S, cp_V);

    const int smem_bytes = SMEM_WORDS * 4;   // 212992
    cudaFuncSetAttribute(fused_lowrank_mlp_kernel,
                         cudaFuncAttributeMaxDynamicSharedMemorySize, smem_bytes);
    fused_lowrank_mlp_kernel<<<TOKENS / MT, 256, smem_bytes>>>(x, cfc_b, cp_b, out);
}

// round 9
// speedup vs baseline: 1.3262x; 1.0467x over previous
#include <cuda_runtime.h>
#include <cstdint>
#include <math.h>

#define TOKENS 8192
#define DMODEL 1024
#define DFF    4096
#define RANK   128
#define MT     64

// smem strides in words; both == 16 (mod 32) -> conflict-free LDS.128 fragments
#define SK128 144
#define SK64  80
// smem word offsets
#define W_SA  0                    // t1 / t2 tile: 64 x 144 = 9216
#define W_WB0 9216                 // staging buffer 0 (19456 words)
#define W_WB1 28672                // staging buffer 1
#define WB_U  9216                 // U-part offset inside a staging buffer
#define SMEM_WORDS 48128           // 192512 bytes

// ---- k-permuted tf32 weight scratch (prep outputs) ----
__device__ uint32_t g_v1[DFF * RANK];      // cfc_V          [f][perm(r)]
__device__ uint32_t g_v2[DMODEL * RANK];   // cp_V           [d][perm(r)]
__device__ uint32_t g_u1t[RANK * DMODEL];  // (cfc_U*S)^T    [r][perm(d)]
__device__ uint32_t g_u2t[RANK * DFF];     // (cp_U*S2)^T    [r][perm(f)]

__device__ __forceinline__ int pcid(int c) {           // permute low 4 bits
    return (c & ~15) | ((c & 3) << 2) | ((c >> 2) & 3);
}
__device__ __forceinline__ uint32_t f2tf(float f) {
    uint32_t u; asm("cvt.rna.tf32.f32 %0, %1;" : "=r"(u) : "f"(f)); return u;
}
__device__ __forceinline__ float gelu_exact(float v) {
    return 0.5f * v * (1.f + erff(v * 0.7071067811865476f));
}
__device__ __forceinline__ void mma8(float* c,
                                     uint32_t a0, uint32_t a1, uint32_t a2, uint32_t a3,
                                     uint32_t b0, uint32_t b1) {
    asm volatile(
        "mma.sync.aligned.m16n8k8.row.col.f32.tf32.tf32.f32 "
        "{%0,%1,%2,%3}, {%4,%5,%6,%7}, {%8,%9}, {%0,%1,%2,%3};\n"
        : "+f"(c[0]), "+f"(c[1]), "+f"(c[2]), "+f"(c[3])
        : "r"(a0), "r"(a1), "r"(a2), "r"(a3), "r"(b0), "r"(b1));
}
__device__ __forceinline__ void cpa16(uint32_t dst, const void* src) {
    asm volatile("cp.async.cg.shared.global [%0], [%1], 16;\n" :: "r"(dst), "l"(src) : "memory");
}
#define CPA_COMMIT() asm volatile("cp.async.commit_group;\n" ::: "memory")
#define CPA_WAIT1()  asm volatile("cp.async.wait_group 1;\n" ::: "memory")

// Warp GEMM piece: mt=2 fixed (rows mrow..mrow+31), NT n-tiles of 8,
// KP k-pairs (K = KP*16). A,B in k-permuted layout; one LDS.128 feeds 2 k-steps.
template<int NT, int KP, int SA_, int SB_>
__device__ __forceinline__ void gemm_tile(const uint32_t* __restrict__ A,
                                          const uint32_t* __restrict__ B,
                                          int mrow, int ncol, int qr, int qc,
                                          float (*acc)[4])
{
    #pragma unroll
    for (int kp = 0; kp < KP; kp++) {
        const int kb = kp * 16 + qc * 4;
        uint4 a[4];
        #pragma unroll
        for (int mi = 0; mi < 2; mi++) {
            a[mi * 2 + 0] = *(const uint4*)(A + (mrow + mi * 16 + qr)     * SA_ + kb);
            a[mi * 2 + 1] = *(const uint4*)(A + (mrow + mi * 16 + qr + 8) * SA_ + kb);
        }
        uint4 b[NT];
        #pragma unroll
        for (int nt = 0; nt < NT; nt++)
            b[nt] = *(const uint4*)(B + (ncol + nt * 8 + qr) * SB_ + kb);
        #pragma unroll
        for (int mi = 0; mi < 2; mi++)
            #pragma unroll
            for (int nt = 0; nt < NT; nt++) {
                float* c = acc[mi * NT + nt];
                mma8(c, a[mi*2].x, a[mi*2+1].x, a[mi*2].y, a[mi*2+1].y, b[nt].x, b[nt].y);
                mma8(c, a[mi*2].z, a[mi*2+1].z, a[mi*2].w, a[mi*2+1].w, b[nt].z, b[nt].w);
            }
    }
}

// ---------------- prep: convert weights to tf32, fold S, transpose, k-permute ----------------
__global__ void prep_w_kernel(const float* __restrict__ cfc_U, const float* __restrict__ cfc_S,
                              const float* __restrict__ cfc_V,
                              const float* __restrict__ cp_U,  const float* __restrict__ cp_S,
                              const float* __restrict__ cp_V) {
    int b = blockIdx.x, t = threadIdx.x;
    if (b < 512) {                       // g_v1: [f][perm(r)]
        int i = b * 256 + t;
        int row = i >> 5, j = i & 31;
        float4 v = ((const float4*)cfc_V)[i];
        uint32_t* d = g_v1 + (size_t)row * RANK;
        int c = j * 4;
        d[pcid(c + 0)] = f2tf(v.x); d[pcid(c + 1)] = f2tf(v.y);
        d[pcid(c + 2)] = f2tf(v.z); d[pcid(c + 3)] = f2tf(v.w);
    } else if (b < 640) {                // g_v2: [d][perm(r)]
        int i = (b - 512) * 256 + t;
        int row = i >> 5, j = i & 31;
        float4 v = ((const float4*)cp_V)[i];
        uint32_t* d = g_v2 + (size_t)row * RANK;
        int c = j * 4;
        d[pcid(c + 0)] = f2tf(v.x); d[pcid(c + 1)] = f2tf(v.y);
        d[pcid(c + 2)] = f2tf(v.z); d[pcid(c + 3)] = f2tf(v.w);
    } else if (b < 1152) {               // g_u1t: [r][perm(d)] = U1[d][r]*S[r]
        int o = (b - 640) * 256 + t;
        int r = o >> 10, d = o & 1023;
        g_u1t[(size_t)r * DMODEL + pcid(d)] = f2tf(cfc_U[(size_t)d * RANK + r] * cfc_S[r]);
    } else {                             // g_u2t: [r][perm(f)] = U2[f][r]*S2[r]
        int o = (b - 1152) * 256 + t;
        int r = o >> 12, f = o & 4095;
        g_u2t[(size_t)r * DFF + pcid(f)] = f2tf(cp_U[(size_t)f * RANK + r] * cp_S[r]);
    }
}

// ---------------- main fused kernel ----------------
__global__ void __launch_bounds__(256, 1)
fused_lowrank_mlp_kernel(const float* __restrict__ x,
                         const float* __restrict__ cfc_b,
                         const float* __restrict__ cp_b,
                         float* __restrict__ out)
{
    extern __shared__ uint32_t sm[];
    uint32_t* SA = sm + W_SA;
    uint32_t* WB[2] = { sm + W_WB0, sm + W_WB1 };
    const uint32_t smb = (uint32_t)__cvta_generic_to_shared(sm);
    const uint32_t WBA[2] = { smb + W_WB0 * 4u, smb + W_WB1 * 4u };

    const int tid  = threadIdx.x;
    const int lane = tid & 31;
    const int warp = tid >> 5;
    const int qr   = lane >> 2;
    const int qc   = lane & 3;
    const int mg   = warp & 1;          // 2 row groups of 32
    const int ng   = warp >> 1;         // 4 col groups
    const int mrow = mg * 32;
    const int m0   = blockIdx.x * MT;

    // ---- staging helpers ----
    auto stage_u1 = [&](int ci, int b) {     // U1 chunk [128 r x 64 d]
        const uint32_t* src = g_u1t + ci * 64;
        #pragma unroll
        for (int i = 0; i < 8; i++) {
            int u = tid + i * 256; int row = u >> 4, p = u & 15;
            cpa16(WBA[b] + (WB_U + row * SK64 + p * 4) * 4u,
                  src + (size_t)row * DMODEL + p * 4);
        }
    };
    auto stage_2 = [&](int it, int b) {      // V1 [64f x 128r] + U2 [128r x 64f]
        const uint32_t* sv = g_v1 + (size_t)it * 64 * RANK;
        #pragma unroll
        for (int i = 0; i < 8; i++) {
            int u = tid + i * 256; int row = u >> 5, p = u & 31;
            cpa16(WBA[b] + (row * SK128 + p * 4) * 4u, sv + (size_t)row * RANK + p * 4);
        }
        const uint32_t* su = g_u2t + it * 64;
        #pragma unroll
        for (int i = 0; i < 8; i++) {
            int u = tid + i * 256; int row = u >> 4, p = u & 15;
            cpa16(WBA[b] + (WB_U + row * SK64 + p * 4) * 4u,
                  su + (size_t)row * DFF + p * 4);
        }
    };
    auto stage_3 = [&](int dc, int b) {      // V2 [64 d x 128 r]
        const uint32_t* sv = g_v2 + (size_t)dc * 64 * RANK;
        #pragma unroll
        for (int i = 0; i < 8; i++) {
            int u = tid + i * 256; int row = u >> 5, p = u & 31;
            cpa16(WBA[b] + (row * SK128 + p * 4) * 4u, sv + (size_t)row * RANK + p * 4);
        }
    };

    // x chunk [64 tok x 64 d]: LDG float4 -> regs; STS permuted tf32
    float4 xr[4];
    auto ldx = [&](int ci) {
        if (ci < 16) {
            #pragma unroll
            for (int i = 0; i < 4; i++) {
                int idx = tid + i * 256; int row = idx >> 4, j = idx & 15;
                xr[i] = *(const float4*)(x + (size_t)(m0 + row) * DMODEL + ci * 64 + j * 4);
            }
        }
    };
    auto stx = [&](int b) {
        #pragma unroll
        for (int i = 0; i < 4; i++) {
            int idx = tid + i * 256; int row = idx >> 4, j = idx & 15;
            uint32_t* d = WB[b] + row * SK64 + (j >> 2) * 16 + (j & 3);
            d[0]  = f2tf(xr[i].x);
            d[4]  = f2tf(xr[i].y);
            d[8]  = f2tf(xr[i].z);
            d[12] = f2tf(xr[i].w);
        }
    };

    // ================= Phase 1: t1[64x128] = x @ (U1*S) =================
    float acc1[8][4];
    #pragma unroll
    for (int i = 0; i < 8; i++)
        #pragma unroll
        for (int j = 0; j < 4; j++) acc1[i][j] = 0.f;

    ldx(0); stx(0); stage_u1(0, 0); CPA_COMMIT();
    ldx(1); stx(1); stage_u1(1, 1); CPA_COMMIT();
    ldx(2);

    for (int ci = 0; ci < 16; ci++) {
        int b = ci & 1;
        CPA_WAIT1();
        __syncthreads();
        gemm_tile<4, 4, SK64, SK64>(WB[b], WB[b] + WB_U, mrow, ng * 32, qr, qc, acc1);
        __syncthreads();
        if (ci + 2 < 16) { stx(b); stage_u1(ci + 2, b); }
        CPA_COMMIT();
        ldx(ci + 3);
    }

    // t1 epilogue -> SA (k-permuted, stride 144)
    #pragma unroll
    for (int mi = 0; mi < 2; mi++)
        #pragma unroll
        for (int nt = 0; nt < 4; nt++) {
            int c0 = ng * 32 + nt * 8 + 2 * qc;
            int r0 = mrow + mi * 16 + qr;
            float* a = acc1[mi * 4 + nt];
            SA[r0 * SK128 + pcid(c0)]           = f2tf(a[0]);
            SA[r0 * SK128 + pcid(c0 + 1)]       = f2tf(a[1]);
            SA[(r0 + 8) * SK128 + pcid(c0)]     = f2tf(a[2]);
            SA[(r0 + 8) * SK128 + pcid(c0 + 1)] = f2tf(a[3]);
        }

    stage_2(0, 0); CPA_COMMIT();
    stage_2(1, 1); CPA_COMMIT();

    // ===== Phase 2: 64 f-chunks; each warp accumulates a PARTIAL t2[32x128]
    //       over its own 16-f slab in registers; one smem reduction at end =====
    float t2a[128];                     // [mi(2)][nt(16)][4]
    #pragma unroll
    for (int i = 0; i < 128; i++) t2a[i] = 0.f;

    const unsigned FULL = 0xffffffffu;
    const int sl0 = qr * 4 + (qc >> 1);      // shuffle source lanes
    const int sl2 = sl0 + 2;
    const bool odd = qc & 1;

    for (int it = 0; it < 64; it++) {
        int b = it & 1;
        CPA_WAIT1();
        __syncthreads();

        // GEMM2: h[64x64] = t1 @ V1c^T (K=128); warp tile 32x16 (own f-cols ng*16..+16)
        float ha[4][4];
        #pragma unroll
        for (int i = 0; i < 4; i++)
            #pragma unroll
            for (int j = 0; j < 4; j++) ha[i][j] = 0.f;
        gemm_tile<2, 8, SK128, SK128>(SA, WB[b], mrow, ng * 16, qr, qc, ha);

        // bias + exact GELU on C-layout regs
        #pragma unroll
        for (int mi = 0; mi < 2; mi++)
            #pragma unroll
            for (int nt = 0; nt < 2; nt++) {
                int fb = it * 64 + ng * 16 + nt * 8 + 2 * qc;
                float b0 = __ldg(cfc_b + fb), b1 = __ldg(cfc_b + fb + 1);
                float* a = ha[mi * 2 + nt];
                a[0] = gelu_exact(a[0] + b0);
                a[1] = gelu_exact(a[1] + b1);
                a[2] = gelu_exact(a[2] + b0);
                a[3] = gelu_exact(a[3] + b1);
            }

        // C-layout -> A-fragment layout via intra-warp shuffles (rows align; cols permute)
        uint32_t af[4][4];               // [mi*2+kg][a0..a3], tf32 bits
        #pragma unroll
        for (int mi = 0; mi < 2; mi++)
            #pragma unroll
            for (int kg = 0; kg < 2; kg++) {
                float* h4 = ha[mi * 2 + kg];
                float u0 = __shfl_sync(FULL, h4[0], sl0);
                float u1 = __shfl_sync(FULL, h4[1], sl0);
                float u2 = __shfl_sync(FULL, h4[2], sl0);
                float u3 = __shfl_sync(FULL, h4[3], sl0);
                float w0 = __shfl_sync(FULL, h4[0], sl2);
                float w1 = __shfl_sync(FULL, h4[1], sl2);
                float w2 = __shfl_sync(FULL, h4[2], sl2);
                float w3 = __shfl_sync(FULL, h4[3], sl2);
                af[mi * 2 + kg][0] = f2tf(odd ? u1 : u0);   // (row qr,   k qc)
                af[mi * 2 + kg][1] = f2tf(odd ? u3 : u2);   // (row qr+8, k qc)
                af[mi * 2 + kg][2] = f2tf(odd ? w1 : w0);   // (row qr,   k qc+4)
                af[mi * 2 + kg][3] = f2tf(odd ? w3 : w2);   // (row qr+8, k qc+4)
            }

        // GEMM3 (register A): t2_partial[32x128] += h_slab(16f) @ U2c
        {
            const uint32_t* up = WB[b] + WB_U;
            const int kb = ng * 16 + qc * 4;    // warp's own 16-f slab in U2 chunk
            #pragma unroll
            for (int nt = 0; nt < 16; nt++) {
                uint4 bv = *(const uint4*)(up + (nt * 8 + qr) * SK64 + kb);
                #pragma unroll
                for (int mi = 0; mi < 2; mi++) {
                    float* c = t2a + (mi * 16 + nt) * 4;
                    mma8(c, af[mi*2][0], af[mi*2][1], af[mi*2][2], af[mi*2][3], bv.x, bv.y);
                    mma8(c, af[mi*2+1][0], af[mi*2+1][1], af[mi*2+1][2], af[mi*2+1][3], bv.z, bv.w);
                }
            }
        }
        __syncthreads();
        if (it + 2 < 64) stage_2(it + 2, b);
        CPA_COMMIT();
    }

    // ---- t2 reduction: 4 partials per m-group -> SA (tf32, k-permuted) ----
    {
        uint32_t* RS = sm + W_WB0;           // 32768-word scratch (WB region, now free)
        int base = (mg * 4 + ng) * 4096;
        #pragma unroll
        for (int mi = 0; mi < 2; mi++)
            #pragma unroll
            for (int nt = 0; nt < 16; nt++) {
                int rl = mi * 16 + qr, c0 = nt * 8 + 2 * qc;
                float* a = t2a + (mi * 16 + nt) * 4;
                RS[base + rl * 128 + c0]           = __float_as_uint(a[0]);
                RS[base + rl * 128 + c0 + 1]       = __float_as_uint(a[1]);
                RS[base + (rl + 8) * 128 + c0]     = __float_as_uint(a[2]);
                RS[base + (rl + 8) * 128 + c0 + 1] = __float_as_uint(a[3]);
            }
        __syncthreads();
        #pragma unroll
        for (int i = 0; i < 32; i++) {
            int e = tid + i * 256;
            int row = e >> 7, col = e & 127;
            int gb = (row >> 5) * 4, rl = row & 31;
            float s = __uint_as_float(RS[(gb + 0) * 4096 + rl * 128 + col])
                    + __uint_as_float(RS[(gb + 1) * 4096 + rl * 128 + col])
                    + __uint_as_float(RS[(gb + 2) * 4096 + rl * 128 + col])
                    + __uint_as_float(RS[(gb + 3) * 4096 + rl * 128 + col]);
            SA[row * SK128 + pcid(col)] = f2tf(s);
        }
        __syncthreads();
    }

    stage_3(0, 0); CPA_COMMIT();
    stage_3(1, 1); CPA_COMMIT();

    // ================= Phase 3: out = t2 @ V2^T + b2 =================
    for (int dc = 0; dc < 16; dc++) {
        int b = dc & 1;
        CPA_WAIT1();
        __syncthreads();

        float oa[4][4];
        #pragma unroll
        for (int i = 0; i < 4; i++)
            #pragma unroll
            for (int j = 0; j < 4; j++) oa[i][j] = 0.f;
        gemm_tile<2, 8, SK128, SK128>(SA, WB[b], mrow, ng * 16, qr, qc, oa);

        #pragma unroll
        for (int mi = 0; mi < 2; mi++)
            #pragma unroll
            for (int nt = 0; nt < 2; nt++) {
                int c0 = ng * 16 + nt * 8 + 2 * qc;
                int db = dc * 64 + c0;
                float b0 = __ldg(cp_b + db), b1 = __ldg(cp_b + db + 1);
                int r0 = m0 + mrow + mi * 16 + qr;
                float* a = oa[mi * 2 + nt];
                *(float2*)(out + (size_t)r0 * DMODEL + db) =
                    make_float2(a[0] + b0, a[1] + b1);
                *(float2*)(out + (size_t)(r0 + 8) * DMODEL + db) =
                    make_float2(a[2] + b0, a[3] + b1);
            }
        __syncthreads();
        if (dc + 2 < 16) stage_3(dc + 2, b);
        CPA_COMMIT();
    }
}

extern "C" void kernel_launch(void* const* d_in, const int* in_sizes, int n_in,
                              void* d_out, int out_size)
{
    const float* x     = (const float*)d_in[0];
    const float* cfc_U = (const float*)d_in[1];
    const float* cfc_S = (const float*)d_in[2];
    const float* cfc_V = (const float*)d_in[3];
    const float* cfc_b = (const float*)d_in[4];
    const float* cp_U  = (const float*)d_in[5];
    const float* cp_S  = (const float*)d_in[6];
    const float* cp_V  = (const float*)d_in[7];
    const float* cp_b  = (const float*)d_in[8];
    float* out = (float*)d_out;

    prep_w_kernel<<<3200, 256>>>(cfc_U, cfc_S, cfc_V, cp_U, cp_S, cp_V);

    const int smem_bytes = SMEM_WORDS * 4;   // 192512
    cudaFuncSetAttribute(fused_lowrank_mlp_kernel,
                         cudaFuncAttributeMaxDynamicSharedMemorySize, smem_bytes);
    fused_lowrank_mlp_kernel<<<TOKENS / MT, 256, smem_bytes>>>(x, cfc_b, cp_b, out);
}